// round 1
// baseline (speedup 1.0000x reference)
#include <cuda_runtime.h>

// YOLOv1 loss on GB300.
// Inputs: pred [B,7,7,30] f32, target [B,7,7,30] f32. Output: 4 f32 scalars
// (batch_loss, batch_cls_loss, batch_obj_loss, batch_coord_loss).

#define CELLS 49
#define ELEMS 1470            // 49*30
#define NBOX 98
#define MAXB 8192
#define NOOBJ_LAMBDA 0.5
#define COORD_LAMBDA 5.0

// partials[b][0]=noobj, [1]=cls, [2]=coord(cxcy+wh), [3]=obj
__device__ float g_partials[MAXB * 4];

__global__ void __launch_bounds__(128)
yolo_loss_part(const float* __restrict__ pred, const float* __restrict__ targ)
{
    int b = blockIdx.x;
    const float* p = pred + (size_t)b * ELEMS;
    const float* t = targ + (size_t)b * ELEMS;

    __shared__ float sp[ELEMS];
    __shared__ float st[ELEMS];
    __shared__ float pbox[NBOX][5];   // x1,y1,x2,y2,area (pred)
    __shared__ float tbox[NBOX][5];   // x1,y1,x2,y2,area (target)
    __shared__ int   objlist[NBOX];
    __shared__ int   cnt;
    __shared__ unsigned char bmask[NBOX];

    int tid = threadIdx.x;
    if (tid == 0) cnt = 0;

    // coalesced float2 load (1470 floats = 735 float2; base is 8B-aligned:
    // b*5880 bytes divisible by 8)
    {
        const float2* p2 = reinterpret_cast<const float2*>(p);
        const float2* t2 = reinterpret_cast<const float2*>(t);
        for (int i = tid; i < ELEMS / 2; i += 128) {
            float2 v = p2[i];
            sp[2 * i]     = v.x;
            sp[2 * i + 1] = v.y;
            float2 w = t2[i];
            st[2 * i]     = w.x;
            st[2 * i + 1] = w.y;
        }
    }
    __syncthreads();

    // per-box precompute: xyxy + area, obj mask, compacted obj list
    if (tid < NBOX) {
        int cell = tid >> 1;
        int off  = (tid & 1) * 5;
        const float* pb = &sp[cell * 30 + off];
        const float* tb = &st[cell * 30 + off];

        {
            float cx = pb[0], cy = pb[1], w = pb[2], h = pb[3];
            float x1 = cx - w * 0.5f, y1 = cy - h * 0.5f;
            float x2 = cx + w * 0.5f, y2 = cy + h * 0.5f;
            pbox[tid][0] = x1; pbox[tid][1] = y1;
            pbox[tid][2] = x2; pbox[tid][3] = y2;
            pbox[tid][4] = (x2 - x1) * (y2 - y1);
        }
        {
            float cx = tb[0], cy = tb[1], w = tb[2], h = tb[3];
            float x1 = cx - w * 0.5f, y1 = cy - h * 0.5f;
            float x2 = cx + w * 0.5f, y2 = cy + h * 0.5f;
            tbox[tid][0] = x1; tbox[tid][1] = y1;
            tbox[tid][2] = x2; tbox[tid][3] = y2;
            tbox[tid][4] = (x2 - x1) * (y2 - y1);
        }

        bool obj = st[cell * 30 + 4] > 0.0f;
        bmask[tid] = obj ? 1 : 0;
        if (obj) {
            int pos = atomicAdd(&cnt, 1);
            objlist[pos] = tid;
        }
    }
    __syncthreads();

    float acc_noobj = 0.0f, acc_cls = 0.0f, acc_coord = 0.0f, acc_obj = 0.0f;

    // per-cell: noobj confidence loss or class loss
    if (tid < CELLS) {
        int base = tid * 30;
        float ct = st[base + 4];
        if (ct == 0.0f) {
            float d4 = sp[base + 4] - st[base + 4];
            float d9 = sp[base + 9] - st[base + 9];
            acc_noobj = d4 * d4 + d9 * d9;
        } else {
            float s = 0.0f;
            #pragma unroll
            for (int k = 10; k < 30; k++) {
                float d = sp[base + k] - st[base + k];
                s += d * d;
            }
            acc_cls = s;
        }
    }

    // per target box: max IOU over obj pred boxes -> cmask -> coord/obj losses
    if (tid < NBOX && bmask[tid]) {
        int k = tid;
        float tx1 = tbox[k][0], ty1 = tbox[k][1];
        float tx2 = tbox[k][2], ty2 = tbox[k][3];
        float tarea = tbox[k][4];
        float maxiou = 0.0f;
        int n = cnt;
        for (int ii = 0; ii < n; ii++) {
            int j = objlist[ii];
            float lx = fmaxf(pbox[j][0], tx1);
            float ly = fmaxf(pbox[j][1], ty1);
            float rx = fminf(pbox[j][2], tx2);
            float ry = fminf(pbox[j][3], ty2);
            float iw = fmaxf(rx - lx, 0.0f);
            float ih = fmaxf(ry - ly, 0.0f);
            float inter = iw * ih;
            float uni = pbox[j][4] + tarea - inter;
            float iou = inter / (uni > 0.0f ? uni : 1.0f);
            maxiou = fmaxf(maxiou, iou);
        }
        if (maxiou != 0.0f) {
            int cell = k >> 1;
            int off  = (k & 1) * 5;
            const float* pb = &sp[cell * 30 + off];
            const float* tb = &st[cell * 30 + off];
            float dx = pb[0] - tb[0];
            float dy = pb[1] - tb[1];
            float dw = sqrtf(pb[2]) - sqrtf(tb[2]);
            float dh = sqrtf(pb[3]) - sqrtf(tb[3]);
            acc_coord = dx * dx + dy * dy + dw * dw + dh * dh;
            float dc = pb[4] - tb[4];
            acc_obj = dc * dc;
        }
    }

    // block reduce 4 accumulators across 128 threads
    #pragma unroll
    for (int o = 16; o > 0; o >>= 1) {
        acc_noobj += __shfl_down_sync(0xffffffffu, acc_noobj, o);
        acc_cls   += __shfl_down_sync(0xffffffffu, acc_cls, o);
        acc_coord += __shfl_down_sync(0xffffffffu, acc_coord, o);
        acc_obj   += __shfl_down_sync(0xffffffffu, acc_obj, o);
    }
    __shared__ float red[4][4];
    int warp = tid >> 5, lane = tid & 31;
    if (lane == 0) {
        red[0][warp] = acc_noobj;
        red[1][warp] = acc_cls;
        red[2][warp] = acc_coord;
        red[3][warp] = acc_obj;
    }
    __syncthreads();
    if (tid == 0) {
        g_partials[b * 4 + 0] = red[0][0] + red[0][1] + red[0][2] + red[0][3];
        g_partials[b * 4 + 1] = red[1][0] + red[1][1] + red[1][2] + red[1][3];
        g_partials[b * 4 + 2] = red[2][0] + red[2][1] + red[2][2] + red[2][3];
        g_partials[b * 4 + 3] = red[3][0] + red[3][1] + red[3][2] + red[3][3];
    }
}

__global__ void __launch_bounds__(256)
yolo_loss_reduce(int B, float* __restrict__ out)
{
    int tid = threadIdx.x;
    double s0 = 0.0, s1 = 0.0, s2 = 0.0, s3 = 0.0;
    for (int b = tid; b < B; b += 256) {
        s0 += (double)g_partials[b * 4 + 0];
        s1 += (double)g_partials[b * 4 + 1];
        s2 += (double)g_partials[b * 4 + 2];
        s3 += (double)g_partials[b * 4 + 3];
    }
    #pragma unroll
    for (int o = 16; o > 0; o >>= 1) {
        s0 += __shfl_down_sync(0xffffffffu, s0, o);
        s1 += __shfl_down_sync(0xffffffffu, s1, o);
        s2 += __shfl_down_sync(0xffffffffu, s2, o);
        s3 += __shfl_down_sync(0xffffffffu, s3, o);
    }
    __shared__ double rs[4][8];
    int warp = tid >> 5, lane = tid & 31;
    if (lane == 0) {
        rs[0][warp] = s0; rs[1][warp] = s1; rs[2][warp] = s2; rs[3][warp] = s3;
    }
    __syncthreads();
    if (tid == 0) {
        double n0 = 0, n1 = 0, n2 = 0, n3 = 0;
        #pragma unroll
        for (int w = 0; w < 8; w++) {
            n0 += rs[0][w]; n1 += rs[1][w]; n2 += rs[2][w]; n3 += rs[3][w];
        }
        double invB = 1.0 / (double)B;
        double cls   = n1 * invB;
        double objl  = (n3 + n0 * NOOBJ_LAMBDA) * invB;
        double coord = n2 * COORD_LAMBDA * invB;
        out[0] = (float)(cls + objl + coord);
        out[1] = (float)cls;
        out[2] = (float)objl;
        out[3] = (float)coord;
    }
}

extern "C" void kernel_launch(void* const* d_in, const int* in_sizes, int n_in,
                              void* d_out, int out_size)
{
    const float* pred = (const float*)d_in[0];
    const float* targ = (const float*)d_in[1];
    float* out = (float*)d_out;
    int B = in_sizes[0] / ELEMS;
    if (B > MAXB) B = MAXB;

    yolo_loss_part<<<B, 128>>>(pred, targ);
    yolo_loss_reduce<<<1, 256>>>(B, out);
}

// round 2
// speedup vs baseline: 1.2435x; 1.2435x over previous
#include <cuda_runtime.h>

// YOLOv1 loss, GB300. pred/target [8192,7,7,30] f32 -> 4 f32 scalars.

#define ELEMS 1470
#define MAXB  8192

// per-batch partials: x=noobj, y=cls, z=coord, w=obj
__device__ float4 g_partials[MAXB];

__global__ void __launch_bounds__(128)
yolo_part(const float* __restrict__ pred, const float* __restrict__ targ)
{
    int b   = blockIdx.x;
    int tid = threadIdx.x;

    __shared__ __align__(16) float spb[49][10];   // pred ch0..9 raw
    __shared__ __align__(16) float stb[49][10];   // targ ch0..9 raw
    __shared__ __align__(16) float sdc[49][20];   // pred-targ diff ch10..29
    __shared__ float px1[98], py1[98], px2[98], py2[98], pa[98];
    __shared__ float qx1[98], qy1[98], qx2[98], qy2[98], qa[98];
    __shared__ int   objlist[98];
    __shared__ int   cnt;
    __shared__ unsigned char isobj[98];

    if (tid == 0) cnt = 0;

    const float2* p2 = reinterpret_cast<const float2*>(pred + (size_t)b * ELEMS);
    const float2* t2 = reinterpret_cast<const float2*>(targ + (size_t)b * ELEMS);

    // fused load-transform: 735 float2 per tensor; pair (2i,2i+1) never
    // straddles a cell (30 is even), so cell = i/15, ch = 2*(i%15).
    #pragma unroll 6
    for (int i = tid; i < 735; i += 128) {
        float2 pv = p2[i];
        float2 tv = t2[i];
        int cell = i / 15;
        int ch   = (i - cell * 15) * 2;
        if (ch < 10) {
            spb[cell][ch]     = pv.x;
            spb[cell][ch + 1] = pv.y;
            stb[cell][ch]     = tv.x;
            stb[cell][ch + 1] = tv.y;
        } else {
            sdc[cell][ch - 10] = pv.x - tv.x;
            sdc[cell][ch - 9]  = pv.y - tv.y;
        }
    }
    __syncthreads();

    // per-box xyxy + area, obj flag, compacted obj list
    if (tid < 98) {
        int cell = tid >> 1;
        int off  = (tid & 1) * 5;
        {
            float cx = spb[cell][off],     cy = spb[cell][off + 1];
            float w  = spb[cell][off + 2], h  = spb[cell][off + 3];
            float x1 = cx - w * 0.5f, y1 = cy - h * 0.5f;
            float x2 = cx + w * 0.5f, y2 = cy + h * 0.5f;
            px1[tid] = x1; py1[tid] = y1; px2[tid] = x2; py2[tid] = y2;
            pa[tid]  = (x2 - x1) * (y2 - y1);
        }
        {
            float cx = stb[cell][off],     cy = stb[cell][off + 1];
            float w  = stb[cell][off + 2], h  = stb[cell][off + 3];
            float x1 = cx - w * 0.5f, y1 = cy - h * 0.5f;
            float x2 = cx + w * 0.5f, y2 = cy + h * 0.5f;
            qx1[tid] = x1; qy1[tid] = y1; qx2[tid] = x2; qy2[tid] = y2;
            qa[tid]  = (x2 - x1) * (y2 - y1);
        }
        bool obj = stb[cell][4] > 0.0f;
        isobj[tid] = obj ? 1 : 0;
        if (obj) objlist[atomicAdd(&cnt, 1)] = tid;
    }
    __syncthreads();

    float a0 = 0.0f, a1 = 0.0f, a2 = 0.0f, a3 = 0.0f;  // noobj, cls, coord, obj

    // per-cell: noobj conf loss or class loss
    if (tid < 49) {
        if (stb[tid][4] == 0.0f) {
            float d4 = spb[tid][4] - stb[tid][4];
            float d9 = spb[tid][9] - stb[tid][9];
            a0 = d4 * d4 + d9 * d9;
        } else {
            const float4* c4 = reinterpret_cast<const float4*>(sdc[tid]);
            float s = 0.0f;
            #pragma unroll
            for (int q = 0; q < 5; q++) {
                float4 v = c4[q];
                s += v.x * v.x + v.y * v.y + v.z * v.z + v.w * v.w;
            }
            a1 = s;
        }
    }

    // per target obj box: max IOU over obj pred boxes -> coord/obj losses
    if (tid < 98 && isobj[tid]) {
        float X1 = qx1[tid], Y1 = qy1[tid], X2 = qx2[tid], Y2 = qy2[tid];
        float A  = qa[tid];
        float maxiou = 0.0f;
        int n = cnt;
        for (int ii = 0; ii < n; ii++) {
            int j = objlist[ii];
            float lx = fmaxf(px1[j], X1);
            float ly = fmaxf(py1[j], Y1);
            float rx = fminf(px2[j], X2);
            float ry = fminf(py2[j], Y2);
            float iw = fmaxf(rx - lx, 0.0f);
            float ih = fmaxf(ry - ly, 0.0f);
            float inter = iw * ih;
            float uni = pa[j] + A - inter;
            maxiou = fmaxf(maxiou, inter / (uni > 0.0f ? uni : 1.0f));
        }
        if (maxiou != 0.0f) {
            int cell = tid >> 1;
            int off  = (tid & 1) * 5;
            float dx = spb[cell][off]     - stb[cell][off];
            float dy = spb[cell][off + 1] - stb[cell][off + 1];
            float dw = sqrtf(spb[cell][off + 2]) - sqrtf(stb[cell][off + 2]);
            float dh = sqrtf(spb[cell][off + 3]) - sqrtf(stb[cell][off + 3]);
            a2 = dx * dx + dy * dy + dw * dw + dh * dh;
            float dc = spb[cell][off + 4] - stb[cell][off + 4];
            a3 = dc * dc;
        }
    }

    // block reduce
    #pragma unroll
    for (int o = 16; o > 0; o >>= 1) {
        a0 += __shfl_down_sync(0xffffffffu, a0, o);
        a1 += __shfl_down_sync(0xffffffffu, a1, o);
        a2 += __shfl_down_sync(0xffffffffu, a2, o);
        a3 += __shfl_down_sync(0xffffffffu, a3, o);
    }
    __shared__ float red[4][4];
    int warp = tid >> 5, lane = tid & 31;
    if (lane == 0) {
        red[0][warp] = a0; red[1][warp] = a1; red[2][warp] = a2; red[3][warp] = a3;
    }
    __syncthreads();
    if (tid == 0) {
        float4 r;
        r.x = red[0][0] + red[0][1] + red[0][2] + red[0][3];
        r.y = red[1][0] + red[1][1] + red[1][2] + red[1][3];
        r.z = red[2][0] + red[2][1] + red[2][2] + red[2][3];
        r.w = red[3][0] + red[3][1] + red[3][2] + red[3][3];
        g_partials[b] = r;
    }
}

__global__ void __launch_bounds__(1024)
yolo_reduce(int B, float* __restrict__ out)
{
    int tid = threadIdx.x;
    float s0 = 0.0f, s1 = 0.0f, s2 = 0.0f, s3 = 0.0f;
    for (int i = tid; i < B; i += 1024) {
        float4 v = g_partials[i];
        s0 += v.x; s1 += v.y; s2 += v.z; s3 += v.w;
    }
    #pragma unroll
    for (int o = 16; o > 0; o >>= 1) {
        s0 += __shfl_down_sync(0xffffffffu, s0, o);
        s1 += __shfl_down_sync(0xffffffffu, s1, o);
        s2 += __shfl_down_sync(0xffffffffu, s2, o);
        s3 += __shfl_down_sync(0xffffffffu, s3, o);
    }
    __shared__ float sm[32][4];
    int warp = tid >> 5, lane = tid & 31;
    if (lane == 0) {
        sm[warp][0] = s0; sm[warp][1] = s1; sm[warp][2] = s2; sm[warp][3] = s3;
    }
    __syncthreads();
    if (tid < 32) {
        float t0 = sm[tid][0], t1 = sm[tid][1], t2 = sm[tid][2], t3 = sm[tid][3];
        #pragma unroll
        for (int o = 16; o > 0; o >>= 1) {
            t0 += __shfl_down_sync(0xffffffffu, t0, o);
            t1 += __shfl_down_sync(0xffffffffu, t1, o);
            t2 += __shfl_down_sync(0xffffffffu, t2, o);
            t3 += __shfl_down_sync(0xffffffffu, t3, o);
        }
        if (tid == 0) {
            double invB  = 1.0 / (double)B;
            double cls   = (double)t1 * invB;
            double objl  = ((double)t3 + (double)t0 * 0.5) * invB;
            double coord = (double)t2 * 5.0 * invB;
            out[0] = (float)(cls + objl + coord);
            out[1] = (float)cls;
            out[2] = (float)objl;
            out[3] = (float)coord;
        }
    }
}

extern "C" void kernel_launch(void* const* d_in, const int* in_sizes, int n_in,
                              void* d_out, int out_size)
{
    const float* pred = (const float*)d_in[0];
    const float* targ = (const float*)d_in[1];
    float* out = (float*)d_out;
    int B = in_sizes[0] / ELEMS;
    if (B > MAXB) B = MAXB;

    yolo_part<<<B, 128>>>(pred, targ);
    yolo_reduce<<<1, 1024>>>(B, out);
}